// round 2
// baseline (speedup 1.0000x reference)
#include <cuda_runtime.h>
#include <math.h>

#define NTAG 36
#define SEQ  512
#define HID  512
#define EMB  512
#define G4   2048   // 4*HID

// ---------------- device scratch (no allocations allowed) ----------------
__device__ __align__(16) float g_embeds[SEQ * EMB];        // 1 MB
__device__ __align__(16) float g_P[SEQ * G4];              // 4 MB: Wih@x + bih + bhh
__device__ __align__(16) float g_h[2][HID];
__device__ __align__(16) float g_c[HID];
__device__ int g_tag_list[NTAG * SEQ];
__device__ int g_tag_cnt[NTAG];
__device__ unsigned g_bar;

__device__ __forceinline__ float sigmoidf_(float x) {
    return 1.0f / (1.0f + __expf(-x));
}
__device__ __forceinline__ float tanhf_(float x) {
    // tanh(x) = 2*sigmoid(2x) - 1 ; __expf is ~2ulp, plenty for 1e-3 tolerance
    return 2.0f / (1.0f + __expf(-2.0f * x)) - 1.0f;
}

// ---------------- init: reset barrier/counters, load h0/c0, group tags ----------------
__global__ void k_init(const float* __restrict__ h0, const float* __restrict__ c0,
                       const int* __restrict__ tags) {
    int j = threadIdx.x;            // 512 threads
    g_h[0][j] = h0[j];
    g_c[j]    = c0[j];
    if (j < NTAG) g_tag_cnt[j] = 0;
    if (j == 0)   g_bar = 0;
    __syncthreads();
    int tag = tags[j];
    int pos = atomicAdd(&g_tag_cnt[tag], 1);
    g_tag_list[tag * SEQ + pos] = j;
}

// ---------------- embedding gather ----------------
__global__ void k_embed(const int* __restrict__ x, const float* __restrict__ emb) {
    int t = blockIdx.x;             // grid 512, block 128
    int row = x[t];
    const float4* src = (const float4*)emb + (size_t)row * (EMB / 4);
    float4* dst = (float4*)g_embeds + (size_t)t * (EMB / 4);
    dst[threadIdx.x] = src[threadIdx.x];
}

// ---------------- precompute P[t] = Wih[tag_t] @ x_t + bih + bhh ----------------
// grid: (36 tags, 8 row-blocks of 256, 32 chunks of 16 timesteps). block 256.
__global__ void __launch_bounds__(256, 5)
k_precompute(const float* __restrict__ Wih,
             const float* __restrict__ bih,
             const float* __restrict__ bhh) {
    __shared__ float4 Xs[16 * 128];   // 16 timesteps x 512 floats = 32 KB
    __shared__ int ts[16];
    int g   = blockIdx.x;
    int cnt = g_tag_cnt[g];
    int c0  = blockIdx.z * 16;
    if (c0 >= cnt) return;            // uniform per CTA
    int m   = min(16, cnt - c0);
    int tid = threadIdx.x;

    if (tid < 16) ts[tid] = (tid < m) ? g_tag_list[g * SEQ + c0 + tid] : 0;
    __syncthreads();

    #pragma unroll
    for (int it = 0; it < 8; ++it) {
        int i = it * 256 + tid;
        int n = i >> 7, kk = i & 127;
        Xs[i] = (n < m) ? ((const float4*)g_embeds)[(size_t)ts[n] * 128 + kk]
                        : make_float4(0.f, 0.f, 0.f, 0.f);
    }
    __syncthreads();

    int r = blockIdx.y * 256 + tid;   // 0..2047
    const float4* wrow = (const float4*)(Wih + ((size_t)g * G4 + r) * EMB);

    float acc[16];
    #pragma unroll
    for (int n = 0; n < 16; ++n) acc[n] = 0.f;

    #pragma unroll 4
    for (int kk = 0; kk < 128; ++kk) {
        float4 w = __ldg(wrow + kk);
        #pragma unroll
        for (int n = 0; n < 16; ++n) {
            float4 xv = Xs[n * 128 + kk];   // warp-broadcast, conflict-free
            acc[n] += w.x * xv.x + w.y * xv.y + w.z * xv.z + w.w * xv.w;
        }
    }

    float bias = bih[g * G4 + r] + bhh[g * G4 + r];
    for (int n = 0; n < m; ++n)
        g_P[(size_t)ts[n] * G4 + r] = acc[n] + bias;
}

// ---------------- persistent recurrent kernel ----------------
// grid 128 CTAs x 512 threads (16 warps). CTA b owns j in [4b, 4b+4).
// warp w: jl = w&3 (which j), gate = w>>2. One 512-length dot per warp per step.
__global__ void __launch_bounds__(512, 1) k_seq(const float* __restrict__ Whh,
                                                const int* __restrict__ tags_g) {
    __shared__ float sred[16];
    __shared__ int stags[SEQ];
    int tid  = threadIdx.x;
    int lane = tid & 31;
    int w    = tid >> 5;          // 0..15
    int jl   = w & 3;
    int gate = w >> 2;
    int b    = blockIdx.x;
    int j    = b * 4 + jl;
    int row  = gate * HID + j;    // row in [0, 2048)

    for (int i = tid; i < SEQ; i += 512) stags[i] = tags_g[i];
    __syncthreads();

    float c = 0.f;
    if (tid < 4) c = g_c[b * 4 + tid];

    // prefetch W row for t = 0
    const float4* wr = (const float4*)(Whh + ((size_t)stags[0] * G4 + row) * HID);
    float4 w0 = __ldg(wr + lane);
    float4 w1 = __ldg(wr + lane + 32);
    float4 w2 = __ldg(wr + lane + 64);
    float4 w3 = __ldg(wr + lane + 96);

    float pi = 0.f, pf = 0.f, pg = 0.f, po = 0.f;

    for (int t = 0; t < SEQ; ++t) {
        // prefetch P for this step (independent of h)
        if (tid < 4) {
            const float* Pt = g_P + (size_t)t * G4 + b * 4 + tid;
            pi = __ldg(Pt);
            pf = __ldg(Pt + 512);
            pg = __ldg(Pt + 1024);
            po = __ldg(Pt + 1536);
        }

        // load h_{t} (bypass L1: written by other SMs last step)
        const float4* hg = (const float4*)g_h[t & 1];
        float4 h0 = __ldcg(hg + lane);
        float4 h1 = __ldcg(hg + lane + 32);
        float4 h2 = __ldcg(hg + lane + 64);
        float4 h3 = __ldcg(hg + lane + 96);

        float acc = w0.x*h0.x + w0.y*h0.y + w0.z*h0.z + w0.w*h0.w;
        acc += w1.x*h1.x + w1.y*h1.y + w1.z*h1.z + w1.w*h1.w;
        acc += w2.x*h2.x + w2.y*h2.y + w2.z*h2.z + w2.w*h2.w;
        acc += w3.x*h3.x + w3.y*h3.y + w3.z*h3.z + w3.w*h3.w;

        // prefetch W row for t+1 (hidden behind reduce + barrier)
        if (t + 1 < SEQ) {
            const float4* wr2 = (const float4*)(Whh + ((size_t)stags[t + 1] * G4 + row) * HID);
            w0 = __ldg(wr2 + lane);
            w1 = __ldg(wr2 + lane + 32);
            w2 = __ldg(wr2 + lane + 64);
            w3 = __ldg(wr2 + lane + 96);
        }

        // warp reduce
        #pragma unroll
        for (int off = 16; off; off >>= 1)
            acc += __shfl_down_sync(0xffffffffu, acc, off);
        if (lane == 0) sred[w] = acc;
        __syncthreads();

        if (tid < 4) {
            float gi = sred[tid]      + pi;
            float gf = sred[4 + tid]  + pf;
            float gg = sred[8 + tid]  + pg;
            float go = sred[12 + tid] + po;
            float iv = sigmoidf_(gi);
            float fv = sigmoidf_(gf);
            float gv = tanhf_(gg);
            float ov = sigmoidf_(go);
            c = fv * c + iv * gv;
            g_h[(t + 1) & 1][b * 4 + tid] = ov * tanhf_(c);
            __threadfence();
        }
        __syncthreads();   // all 4 h writes of this CTA done + fenced

        // grid-wide barrier
        if (tid == 0) {
            __threadfence();
            atomicAdd(&g_bar, 1u);
            unsigned target = (unsigned)gridDim.x * (unsigned)(t + 1);
            volatile unsigned* vb = &g_bar;
            while (*vb < target) { }
            __threadfence();
        }
        __syncthreads();
    }

    if (tid < 4) g_c[b * 4 + tid] = c;
}

// ---------------- final fc + sigmoid + pack outputs ----------------
__global__ void k_final(const float* __restrict__ Wfc, const float* __restrict__ bfc,
                        float* __restrict__ out, int out_size) {
    __shared__ float red[16];
    int tid = threadIdx.x;            // 512 threads
    float hv = g_h[0][tid];           // after step 511, h lives in buffer 0
    float v = hv * Wfc[tid];
    #pragma unroll
    for (int off = 16; off; off >>= 1) v += __shfl_down_sync(0xffffffffu, v, off);
    if ((tid & 31) == 0) red[tid >> 5] = v;
    __syncthreads();
    if (tid < 16) {
        float s = red[tid];
        #pragma unroll
        for (int off = 8; off; off >>= 1) s += __shfl_down_sync(0x0000ffffu, s, off);
        if (tid == 0 && out_size > 0)
            out[0] = sigmoidf_(s + bfc[0]);
    }
    if (1 + tid < out_size)   out[1 + tid]   = hv;
    if (513 + tid < out_size) out[513 + tid] = g_c[tid];
}

// ---------------- launcher ----------------
extern "C" void kernel_launch(void* const* d_in, const int* in_sizes, int n_in,
                              void* d_out, int out_size) {
    const int*   x    = (const int*)d_in[0];
    const int*   tags = (const int*)d_in[1];
    const float* h0   = (const float*)d_in[2];
    const float* c0   = (const float*)d_in[3];
    const float* emb  = (const float*)d_in[4];
    const float* Wih  = (const float*)d_in[5];
    const float* Whh  = (const float*)d_in[6];
    const float* bih  = (const float*)d_in[7];
    const float* bhh  = (const float*)d_in[8];
    const float* Wfc  = (const float*)d_in[9];
    const float* bfc  = (const float*)d_in[10];
    (void)in_sizes; (void)n_in;

    k_init<<<1, 512>>>(h0, c0, tags);
    k_embed<<<512, 128>>>(x, emb);
    k_precompute<<<dim3(NTAG, 8, 32), 256>>>(Wih, bih, bhh);
    k_seq<<<128, 512>>>(Whh, tags);
    k_final<<<1, 512>>>(Wfc, bfc, (float*)d_out, out_size);
}